// round 2
// baseline (speedup 1.0000x reference)
#include <cuda_runtime.h>
#include <cuda_bf16.h>
#include <cstdint>

#define TT 512
#define NN 1024
#define DD 256
#define BM 128
#define LDA 72
#define LDB 72
#define ND  (NN*DD)

// Scratch: __device__ globals (allocation-free rule)
__device__ __nv_bfloat16 g_Whi[DD*DD];
__device__ __nv_bfloat16 g_Wlo[DD*DD];
__device__ float g_e[NN*TT];   // e transposed: [n][t]

// ---------------------------------------------------------------------------
__global__ void prep_w(const float* __restrict__ w) {
    int i = blockIdx.x * 256 + threadIdx.x;
    float v = w[i];
    __nv_bfloat16 h = __float2bfloat16(v);
    g_Whi[i] = h;
    g_Wlo[i] = __float2bfloat16(v - __bfloat162float(h));
}

// ---------------------------------------------------------------------------
__device__ __forceinline__ uint32_t sptr(const void* p) {
    return (uint32_t)__cvta_generic_to_shared(p);
}
__device__ __forceinline__ void ldmx4(uint32_t r[4], uint32_t a) {
    asm volatile("ldmatrix.sync.aligned.m8n8.x4.shared.b16 {%0,%1,%2,%3},[%4];"
                 : "=r"(r[0]), "=r"(r[1]), "=r"(r[2]), "=r"(r[3]) : "r"(a));
}
__device__ __forceinline__ void mma_bf(float c[4], const uint32_t a[4],
                                       uint32_t b0, uint32_t b1) {
    asm volatile("mma.sync.aligned.m16n8k16.row.col.f32.bf16.bf16.f32 "
                 "{%0,%1,%2,%3},{%4,%5,%6,%7},{%8,%9},{%0,%1,%2,%3};"
                 : "+f"(c[0]), "+f"(c[1]), "+f"(c[2]), "+f"(c[3])
                 : "r"(a[0]), "r"(a[1]), "r"(a[2]), "r"(a[3]), "r"(b0), "r"(b1));
}
__device__ __forceinline__ void cpa16(uint32_t d, const void* s) {
    asm volatile("cp.async.cg.shared.global [%0],[%1],16;" :: "r"(d), "l"(s));
}
__device__ __forceinline__ float tanh_fast(float x) {
    float ex = __expf(2.f * x);
    return 1.f - __fdividef(2.f, ex + 1.f);
}
__device__ __forceinline__ uint32_t pack_bf2(float x, float y) {
    __nv_bfloat16 bx = __float2bfloat16(x), by = __float2bfloat16(y);
    return (uint32_t)__bfloat16_as_ushort(bx) |
           ((uint32_t)__bfloat16_as_ushort(by) << 16);
}

// ---------------------------------------------------------------------------
// Pass 1: e[t,n] = score_w . tanh(fc_w @ H_row + fc_b)
// M = T*N rows, 3x-bf16-split GEMM (K=256, Nout=256) + fused epilogue.
// CTA: 128 rows x 256 outs, 512 threads, warp grid 4(m)x4(n), warp tile 32x64.
// ---------------------------------------------------------------------------
__global__ void __launch_bounds__(512, 1)
pass1(const float* __restrict__ H, const float* __restrict__ fc_b,
      const float* __restrict__ scw) {
    extern __shared__ __align__(16) char sm[];
    __nv_bfloat16* sA = (__nv_bfloat16*)sm;       // hi [128][LDA] then lo
    __nv_bfloat16* sB = sA + 2 * BM * LDA;        // 2 bufs x (hi 256xLDB + lo)
    float* s_bias = (float*)(sB + 4 * DD * LDB);
    float* s_sw   = s_bias + DD;
    float* s_ep   = s_sw + DD;                    // [4][128]

    const int tid = threadIdx.x, lane = tid & 31, warp = tid >> 5;
    const int wm = warp >> 2, wn = warp & 3;
    if (tid < DD) { s_bias[tid] = fc_b[tid]; s_sw[tid] = scw[tid]; }

    const long row0 = (long)blockIdx.x * BM;

    float acc[2][8][4];
#pragma unroll
    for (int i = 0; i < 2; i++)
#pragma unroll
        for (int j = 0; j < 8; j++)
#pragma unroll
            for (int k = 0; k < 4; k++) acc[i][j][k] = 0.f;

    float4 pf[4];  // A prefetch registers (1 chunk = 128x64 fp32)

    // ---- helpers ----
    auto issueB = [&](int kc) {
        int kof = kc * 64;
        __nv_bfloat16* buf = sB + (kc & 1) * (2 * DD * LDB);
#pragma unroll
        for (int i = 0; i < 4; i++) {
            int lin = tid + i * 512;          // 0..2047
            int r = lin >> 3, sg = lin & 7;   // row 0..255, 16B seg 0..7
            cpa16(sptr(buf + r * LDB + sg * 8), g_Whi + r * DD + kof + sg * 8);
            cpa16(sptr(buf + DD * LDB + r * LDB + sg * 8),
                  g_Wlo + r * DD + kof + sg * 8);
        }
        asm volatile("cp.async.commit_group;");
    };
    auto loadA = [&](int kc) {
        int kof = kc * 64;
#pragma unroll
        for (int i = 0; i < 4; i++) {
            int lin = tid + i * 512;          // 0..2047
            int r = lin >> 4, sg = lin & 15;  // row 0..127, 4-float seg 0..15
            pf[i] = *(const float4*)(H + (row0 + r) * DD + kof + sg * 4);
        }
    };
    auto stsA = [&]() {
#pragma unroll
        for (int i = 0; i < 4; i++) {
            int lin = tid + i * 512;
            int r = lin >> 4, sg = lin & 15;
            float f[4] = {pf[i].x, pf[i].y, pf[i].z, pf[i].w};
            float hi[4], lo[4];
#pragma unroll
            for (int j = 0; j < 4; j++) {
                hi[j] = __bfloat162float(__float2bfloat16(f[j]));
                lo[j] = f[j] - hi[j];
            }
            uint2 hv = make_uint2(pack_bf2(hi[0], hi[1]), pack_bf2(hi[2], hi[3]));
            uint2 lv = make_uint2(pack_bf2(lo[0], lo[1]), pack_bf2(lo[2], lo[3]));
            *(uint2*)(sA + r * LDA + sg * 4) = hv;
            *(uint2*)(sA + BM * LDA + r * LDA + sg * 4) = lv;
        }
    };

    // fragment address lane-offsets (bytes)
    const uint32_t aoff = ((lane & 15) * LDA + (lane >> 4) * 8) * 2;
    const uint32_t aBase0 = sptr(sA) + (wm * 32 + 0) * LDA * 2 + aoff;
    const uint32_t aBase1 = sptr(sA) + (wm * 32 + 16) * LDA * 2 + aoff;
    const uint32_t ALO = BM * LDA * 2;
    const uint32_t bOff =
        (((lane & 7) + (lane >> 4) * 8) * LDB + ((lane >> 3) & 1) * 8) * 2;
    const uint32_t BLO = DD * LDB * 2;

    auto compute = [&](int kc) {
        uint32_t bufB = sptr(sB) + (uint32_t)((kc & 1) * (2 * DD * LDB * 2));
#pragma unroll
        for (int ks = 0; ks < 4; ks++) {
            const uint32_t kb = ks * 16 * 2;  // byte offset of k-step
            uint32_t ah[2][4], al[2][4];
            ldmx4(ah[0], aBase0 + kb);
            ldmx4(al[0], aBase0 + kb + ALO);
            ldmx4(ah[1], aBase1 + kb);
            ldmx4(al[1], aBase1 + kb + ALO);
#pragma unroll
            for (int nj = 0; nj < 4; nj++) {
                uint32_t ba = bufB + (wn * 64 + nj * 16) * LDB * 2 + kb + bOff;
                uint32_t bh[4], bl[4];
                ldmx4(bh, ba);
                ldmx4(bl, ba + BLO);
#pragma unroll
                for (int mi = 0; mi < 2; mi++) {
                    mma_bf(acc[mi][nj * 2], ah[mi], bh[0], bh[1]);
                    mma_bf(acc[mi][nj * 2], al[mi], bh[0], bh[1]);
                    mma_bf(acc[mi][nj * 2], ah[mi], bl[0], bl[1]);
                    mma_bf(acc[mi][nj * 2 + 1], ah[mi], bh[2], bh[3]);
                    mma_bf(acc[mi][nj * 2 + 1], al[mi], bh[2], bh[3]);
                    mma_bf(acc[mi][nj * 2 + 1], ah[mi], bl[2], bl[3]);
                }
            }
        }
    };

    // ---- mainloop: B double-buffered cp.async, A register-prefetched ----
    issueB(0);
    loadA(0);
#pragma unroll 1
    for (int kc = 0; kc < 4; kc++) {
        __syncthreads();
        stsA();
        if (kc < 3) {
            issueB(kc + 1);
            loadA(kc + 1);
            asm volatile("cp.async.wait_group 1;");
        } else {
            asm volatile("cp.async.wait_group 0;");
        }
        __syncthreads();
        compute(kc);
    }

    // ---- epilogue: tanh + score dot, deterministic reduction ----
    float ep[2][2] = {{0.f, 0.f}, {0.f, 0.f}};
#pragma unroll
    for (int mi = 0; mi < 2; mi++)
#pragma unroll
        for (int ni = 0; ni < 8; ni++)
#pragma unroll
            for (int j = 0; j < 2; j++) {
                int col = wn * 64 + ni * 8 + (lane & 3) * 2 + j;
                float b = s_bias[col], w = s_sw[col];
                ep[mi][0] += tanh_fast(acc[mi][ni][j] + b) * w;
                ep[mi][1] += tanh_fast(acc[mi][ni][2 + j] + b) * w;
            }
#pragma unroll
    for (int mi = 0; mi < 2; mi++)
#pragma unroll
        for (int h = 0; h < 2; h++) {
            float v = ep[mi][h];
            v += __shfl_xor_sync(0xffffffffu, v, 1);
            v += __shfl_xor_sync(0xffffffffu, v, 2);
            ep[mi][h] = v;
        }
    if ((lane & 3) == 0) {
        int r = lane >> 2;
        int base = wn * 128 + wm * 32;
        s_ep[base + r]      = ep[0][0];
        s_ep[base + 8 + r]  = ep[0][1];
        s_ep[base + 16 + r] = ep[1][0];
        s_ep[base + 24 + r] = ep[1][1];
    }
    __syncthreads();
    if (tid < 128) {
        float e = s_ep[tid] + s_ep[128 + tid] + s_ep[256 + tid] + s_ep[384 + tid];
        long R = row0 + tid;
        int t = (int)(R >> 10), n = (int)(R & 1023);
        g_e[n * TT + t] = e;
    }
}

// ---------------------------------------------------------------------------
// Pass 2: causal online-softmax scan. 1 CTA per column n, 64 thr x float4.
// ---------------------------------------------------------------------------
__global__ void __launch_bounds__(64, 16)
scan_k(const float* __restrict__ H, float* __restrict__ C) {
    __shared__ float se[TT];
    const int n = blockIdx.x, tid = threadIdx.x;
    for (int i = tid; i < TT; i += 64) se[i] = g_e[n * TT + i];
    __syncthreads();

    const float* hp = H + (long)n * DD + tid * 4;
    float* cp = C + (long)n * DD + tid * 4;

    float4 b0 = __ldcs((const float4*)hp);
    float4 b1 = __ldcs((const float4*)(hp + ND));

    float m = -1e30f, s = 0.f;
    float4 num = make_float4(0.f, 0.f, 0.f, 0.f);

#pragma unroll 4
    for (int t = 0; t < TT; t++) {
        float4 h = b0;
        b0 = b1;
        if (t + 2 < TT) b1 = __ldcs((const float4*)(hp + (long)(t + 2) * ND));
        float ev = se[t];
        float mn = fmaxf(m, ev);
        float al = __expf(m - mn);
        float p  = __expf(ev - mn);
        s = s * al + p;
        num.x = num.x * al + p * h.x;
        num.y = num.y * al + p * h.y;
        num.z = num.z * al + p * h.z;
        num.w = num.w * al + p * h.w;
        m = mn;
        float ri = __fdividef(1.f, s);
        float4 o = make_float4(num.x * ri, num.y * ri, num.z * ri, num.w * ri);
        __stcs((float4*)(cp + (long)t * ND), o);
    }
}

// ---------------------------------------------------------------------------
extern "C" void kernel_launch(void* const* d_in, const int* in_sizes, int n_in,
                              void* d_out, int out_size) {
    const float* H  = (const float*)d_in[0];
    const float* fw = (const float*)d_in[1];
    const float* fb = (const float*)d_in[2];
    const float* sw = (const float*)d_in[3];
    float* C = (float*)d_out;

    prep_w<<<(DD * DD) / 256, 256>>>(fw);

    int smem = (2 * BM * LDA + 4 * DD * LDB) * 2 + (2 * DD + 512) * 4;
    cudaFuncSetAttribute(pass1, cudaFuncAttributeMaxDynamicSharedMemorySize, smem);
    pass1<<<(TT * NN) / BM, 512, smem>>>(H, fb, sw);

    scan_k<<<NN, 64>>>(H, C);
}

// round 8
// speedup vs baseline: 1.7529x; 1.7529x over previous
#include <cuda_runtime.h>
#include <cuda_bf16.h>
#include <cuda_fp16.h>
#include <cstdint>

#define TT 512
#define NN 1024
#define DD 256
#define BM 128
#define LDA 72
#define LDB 72
#define ND  (NN*DD)

// Scratch: __device__ globals (allocation-free rule)
__device__ __half g_Wh[DD*DD];
__device__ float g_e[NN*TT];   // e transposed: [n][t]

// ---------------------------------------------------------------------------
__global__ void prep_w(const float* __restrict__ w) {
    int i = blockIdx.x * 256 + threadIdx.x;
    g_Wh[i] = __float2half_rn(w[i]);
}

// ---------------------------------------------------------------------------
__device__ __forceinline__ uint32_t sptr(const void* p) {
    return (uint32_t)__cvta_generic_to_shared(p);
}
__device__ __forceinline__ void ldmx4(uint32_t r[4], uint32_t a) {
    asm volatile("ldmatrix.sync.aligned.m8n8.x4.shared.b16 {%0,%1,%2,%3},[%4];"
                 : "=r"(r[0]), "=r"(r[1]), "=r"(r[2]), "=r"(r[3]) : "r"(a));
}
__device__ __forceinline__ void mma_fp16(float c[4], const uint32_t a[4],
                                         uint32_t b0, uint32_t b1) {
    asm volatile("mma.sync.aligned.m16n8k16.row.col.f32.f16.f16.f32 "
                 "{%0,%1,%2,%3},{%4,%5,%6,%7},{%8,%9},{%0,%1,%2,%3};"
                 : "+f"(c[0]), "+f"(c[1]), "+f"(c[2]), "+f"(c[3])
                 : "r"(a[0]), "r"(a[1]), "r"(a[2]), "r"(a[3]), "r"(b0), "r"(b1));
}
__device__ __forceinline__ void cpa16(uint32_t d, const void* s) {
    asm volatile("cp.async.cg.shared.global [%0],[%1],16;" :: "r"(d), "l"(s));
}
__device__ __forceinline__ float tanh_fast(float x) {
    float ex = __expf(2.f * x);
    return 1.f - __fdividef(2.f, ex + 1.f);
}
__device__ __forceinline__ uint32_t pack_h2(float x, float y) {
    __half2 h = __floats2half2_rn(x, y);
    return *(uint32_t*)&h;
}

// ---------------------------------------------------------------------------
// Pass 1: e[t,n] = score_w . tanh(fc_w @ H_row + fc_b)
// Single fp16 MMA pass (RN-rounded operands), fp32 accumulate.
// CTA: 128 rows x 256 outs, 512 threads, warp grid 4(m)x4(n), warp tile 32x64.
// ---------------------------------------------------------------------------
__global__ void __launch_bounds__(512, 1)
pass1(const float* __restrict__ H, const float* __restrict__ fc_b,
      const float* __restrict__ scw) {
    extern __shared__ __align__(16) char sm[];
    __half* sA = (__half*)sm;                 // [128][LDA]
    __half* sB = sA + BM * LDA;               // 2 bufs x [256][LDB]
    float* s_bias = (float*)(sB + 2 * DD * LDB);
    float* s_sw   = s_bias + DD;
    float* s_ep   = s_sw + DD;                // [4][128]

    const int tid = threadIdx.x, lane = tid & 31, warp = tid >> 5;
    const int wm = warp >> 2, wn = warp & 3;
    if (tid < DD) { s_bias[tid] = fc_b[tid]; s_sw[tid] = scw[tid]; }

    const long row0 = (long)blockIdx.x * BM;

    float acc[2][8][4];
#pragma unroll
    for (int i = 0; i < 2; i++)
#pragma unroll
        for (int j = 0; j < 8; j++)
#pragma unroll
            for (int k = 0; k < 4; k++) acc[i][j][k] = 0.f;

    float4 pf[4];  // A prefetch registers (1 chunk = 128x64 fp32)

    // ---- helpers ----
    auto issueB = [&](int kc) {
        int kof = kc * 64;
        __half* buf = sB + (kc & 1) * (DD * LDB);
#pragma unroll
        for (int i = 0; i < 4; i++) {
            int lin = tid + i * 512;          // 0..2047
            int r = lin >> 3, sg = lin & 7;   // row 0..255, 16B seg 0..7
            cpa16(sptr(buf + r * LDB + sg * 8), g_Wh + r * DD + kof + sg * 8);
        }
        asm volatile("cp.async.commit_group;");
    };
    auto loadA = [&](int kc) {
        int kof = kc * 64;
#pragma unroll
        for (int i = 0; i < 4; i++) {
            int lin = tid + i * 512;          // 0..2047
            int r = lin >> 4, sg = lin & 15;  // row 0..127, 4-float seg 0..15
            pf[i] = *(const float4*)(H + (row0 + r) * DD + kof + sg * 4);
        }
    };
    auto stsA = [&]() {
#pragma unroll
        for (int i = 0; i < 4; i++) {
            int lin = tid + i * 512;
            int r = lin >> 4, sg = lin & 15;
            uint2 hv = make_uint2(pack_h2(pf[i].x, pf[i].y),
                                  pack_h2(pf[i].z, pf[i].w));
            *(uint2*)(sA + r * LDA + sg * 4) = hv;
        }
    };

    // fragment address lane-offsets (bytes) — identical mapping to the proven
    // R2 kernel (correctness-validated).
    const uint32_t aoff = ((lane & 15) * LDA + (lane >> 4) * 8) * 2;
    const uint32_t aBase0 = sptr(sA) + (wm * 32 + 0) * LDA * 2 + aoff;
    const uint32_t aBase1 = sptr(sA) + (wm * 32 + 16) * LDA * 2 + aoff;
    const uint32_t bOff =
        (((lane & 7) + (lane >> 4) * 8) * LDB + ((lane >> 3) & 1) * 8) * 2;

    auto compute = [&](int kc) {
        uint32_t bufB = sptr(sB) + (uint32_t)((kc & 1) * (DD * LDB * 2));
#pragma unroll
        for (int ks = 0; ks < 4; ks++) {
            const uint32_t kb = ks * 16 * 2;  // byte offset of k-step
            uint32_t a0[4], a1[4];
            ldmx4(a0, aBase0 + kb);
            ldmx4(a1, aBase1 + kb);
#pragma unroll
            for (int nj = 0; nj < 4; nj++) {
                uint32_t ba = bufB + (wn * 64 + nj * 16) * LDB * 2 + kb + bOff;
                uint32_t b[4];
                ldmx4(b, ba);
                mma_fp16(acc[0][nj * 2],     a0, b[0], b[1]);
                mma_fp16(acc[0][nj * 2 + 1], a0, b[2], b[3]);
                mma_fp16(acc[1][nj * 2],     a1, b[0], b[1]);
                mma_fp16(acc[1][nj * 2 + 1], a1, b[2], b[3]);
            }
        }
    };

    // ---- mainloop: B double-buffered cp.async, A register-prefetched ----
    issueB(0);
    loadA(0);
#pragma unroll 1
    for (int kc = 0; kc < 4; kc++) {
        __syncthreads();
        stsA();
        if (kc < 3) {
            issueB(kc + 1);
            loadA(kc + 1);
            asm volatile("cp.async.wait_group 1;");
        } else {
            asm volatile("cp.async.wait_group 0;");
        }
        __syncthreads();
        compute(kc);
    }

    // ---- epilogue: tanh + score dot, deterministic reduction ----
    float ep[2][2] = {{0.f, 0.f}, {0.f, 0.f}};
#pragma unroll
    for (int mi = 0; mi < 2; mi++)
#pragma unroll
        for (int ni = 0; ni < 8; ni++)
#pragma unroll
            for (int j = 0; j < 2; j++) {
                int col = wn * 64 + ni * 8 + (lane & 3) * 2 + j;
                float b = s_bias[col], w = s_sw[col];
                ep[mi][0] += tanh_fast(acc[mi][ni][j] + b) * w;
                ep[mi][1] += tanh_fast(acc[mi][ni][2 + j] + b) * w;
            }
#pragma unroll
    for (int mi = 0; mi < 2; mi++)
#pragma unroll
        for (int h = 0; h < 2; h++) {
            float v = ep[mi][h];
            v += __shfl_xor_sync(0xffffffffu, v, 1);
            v += __shfl_xor_sync(0xffffffffu, v, 2);
            ep[mi][h] = v;
        }
    if ((lane & 3) == 0) {
        int r = lane >> 2;
        int base = wn * 128 + wm * 32;
        s_ep[base + r]      = ep[0][0];
        s_ep[base + 8 + r]  = ep[0][1];
        s_ep[base + 16 + r] = ep[1][0];
        s_ep[base + 24 + r] = ep[1][1];
    }
    __syncthreads();
    if (tid < 128) {
        float e = s_ep[tid] + s_ep[128 + tid] + s_ep[256 + tid] + s_ep[384 + tid];
        long R = row0 + tid;
        int t = (int)(R >> 10), n = (int)(R & 1023);
        g_e[n * TT + t] = e;
    }
}

// ---------------------------------------------------------------------------
// Pass 2: causal softmax-weighted prefix average, global-max formulation.
// Coefficients (w_t = exp(e_t - M), ri_t = 1/prefix_sum(w)) precomputed in
// smem so the streaming loop is pure FMA + MUL (memory-bound).
// 1 CTA per column n, 64 threads x float4.
// ---------------------------------------------------------------------------
__global__ void __launch_bounds__(64, 16)
scan_k(const float* __restrict__ H, float* __restrict__ C) {
    __shared__ float sw_[TT];   // e -> w
    __shared__ float sri[TT];   // prefix sum -> reciprocal
    __shared__ float red[64];
    const int n = blockIdx.x, tid = threadIdx.x;

    float lm = -1e30f;
    for (int i = tid; i < TT; i += 64) {
        float v = g_e[n * TT + i];
        sw_[i] = v;
        lm = fmaxf(lm, v);
    }
    red[tid] = lm;
    __syncthreads();
    if (tid < 32) {
        float v = fmaxf(red[tid], red[tid + 32]);
#pragma unroll
        for (int off = 16; off > 0; off >>= 1)
            v = fmaxf(v, __shfl_xor_sync(0xffffffffu, v, off));
        red[tid] = v;
    }
    __syncthreads();
    const float M = red[0];
    for (int i = tid; i < TT; i += 64) sw_[i] = __expf(sw_[i] - M);
    __syncthreads();
    if (tid == 0) {
        float s = 0.f;
        for (int t = 0; t < TT; t++) { s += sw_[t]; sri[t] = s; }
    }
    __syncthreads();
    for (int i = tid; i < TT; i += 64) sri[i] = __fdividef(1.f, sri[i]);
    __syncthreads();

    const float* hp = H + (long)n * DD + tid * 4;
    float* cp = C + (long)n * DD + tid * 4;

    float4 b0 = __ldcs((const float4*)hp);
    float4 b1 = __ldcs((const float4*)(hp + ND));

    float4 num = make_float4(0.f, 0.f, 0.f, 0.f);

#pragma unroll 4
    for (int t = 0; t < TT; t++) {
        float4 h = b0;
        b0 = b1;
        if (t + 2 < TT) b1 = __ldcs((const float4*)(hp + (long)(t + 2) * ND));
        float w = sw_[t], ri = sri[t];
        num.x = fmaf(w, h.x, num.x);
        num.y = fmaf(w, h.y, num.y);
        num.z = fmaf(w, h.z, num.z);
        num.w = fmaf(w, h.w, num.w);
        float4 o = make_float4(num.x * ri, num.y * ri, num.z * ri, num.w * ri);
        __stcs((float4*)(cp + (long)t * ND), o);
    }
}

// ---------------------------------------------------------------------------
extern "C" void kernel_launch(void* const* d_in, const int* in_sizes, int n_in,
                              void* d_out, int out_size) {
    const float* H  = (const float*)d_in[0];
    const float* fw = (const float*)d_in[1];
    const float* fb = (const float*)d_in[2];
    const float* sw = (const float*)d_in[3];
    float* C = (float*)d_out;

    prep_w<<<(DD * DD) / 256, 256>>>(fw);

    int smem = (BM * LDA + 2 * DD * LDB) * 2 + (2 * DD + 512) * 4;
    cudaFuncSetAttribute(pass1, cudaFuncAttributeMaxDynamicSharedMemorySize, smem);
    pass1<<<(TT * NN) / BM, 512, smem>>>(H, fb, sw);

    scan_k<<<NN, 64>>>(H, C);
}